// round 16
// baseline (speedup 1.0000x reference)
#include <cuda_runtime.h>
#include <cuda_bf16.h>
#include <cuda_fp16.h>
#include <math.h>
#include <stdint.h>

#define NN 20000
#define EE 160000
#define OUTD 256
#define INDIM 256
#define NH 8

typedef unsigned long long ull;

// ---------------- scratch (device globals; no allocation allowed) ----------------
__device__ float g_Q[NN * OUTD];
__device__ __half g_KMh[(size_t)NN * 512];     // per node: [0,256)=k hi fp16, [256,512)=mk fp16
__device__ __half g_Klo[(size_t)NN * 256];     // k lo fp16
__device__ __half g_Vhi[(size_t)NN * 256];
__device__ __half g_Vlo[(size_t)NN * 256];
__device__ __half g_VC[(size_t)3 * NN * 512];  // per (etype,node): [0,256)=val, [256,512)=cval
__device__ float2 g_E[3 * EE * NH];            // (ea, eca) per edge-head
__device__ float2 g_S[3 * NN * NH];            // (sum_ea, sum_eca) per dst-head
// bf16 hi/lo splits for tensor-core GEMM
__device__ __nv_bfloat16 g_xhi[NN * INDIM];
__device__ __nv_bfloat16 g_xlo[NN * INDIM];
__device__ __nv_bfloat16 g_wthi[768 * INDIM];   // [out_col][k] transposed
__device__ __nv_bfloat16 g_wtlo[768 * INDIM];
// transposed+split transform matrices: row index = h*288 + sg*96 + c, 32 d per row
__device__ __half g_Bth[NH * 288 * 32];
__device__ __half g_Btl[NH * 288 * 32];

// ---------------- helpers ----------------
__device__ __forceinline__ float dot4(float4 a, float4 b) {
    return a.x * b.x + a.y * b.y + a.z * b.z + a.w * b.w;
}
__device__ __forceinline__ void red_add_v4(float* p, float a, float b, float c, float d) {
    asm volatile("red.global.add.v4.f32 [%0], {%1,%2,%3,%4};"
                 :: "l"(p), "f"(a), "f"(b), "f"(c), "f"(d) : "memory");
}
__device__ __forceinline__ void red_add_v2(float2* p, float a, float b) {
    asm volatile("red.global.add.v2.f32 [%0], {%1,%2};"
                 :: "l"(p), "f"(a), "f"(b) : "memory");
}
__device__ __forceinline__ uint32_t smem_to_u32(const void* p) {
    uint32_t a;
    asm("{ .reg .u64 t; cvta.to.shared.u64 t, %1; cvt.u32.u64 %0, t; }" : "=r"(a) : "l"(p));
    return a;
}
__device__ __forceinline__ void ldsm_x4(uint32_t* r, uint32_t addr) {
    asm volatile("ldmatrix.sync.aligned.m8n8.x4.shared.b16 {%0,%1,%2,%3}, [%4];"
        : "=r"(r[0]), "=r"(r[1]), "=r"(r[2]), "=r"(r[3]) : "r"(addr));
}
__device__ __forceinline__ void mma_bf16(float* c, const uint32_t* a, const uint32_t* b) {
    asm volatile("mma.sync.aligned.m16n8k16.row.col.f32.bf16.bf16.f32 "
        "{%0,%1,%2,%3}, {%4,%5,%6,%7}, {%8,%9}, {%0,%1,%2,%3};"
        : "+f"(c[0]), "+f"(c[1]), "+f"(c[2]), "+f"(c[3])
        : "r"(a[0]), "r"(a[1]), "r"(a[2]), "r"(a[3]), "r"(b[0]), "r"(b[1]));
}
__device__ __forceinline__ void mma_f16(float* c, const uint32_t* a, const uint32_t* b) {
    asm volatile("mma.sync.aligned.m16n8k16.row.col.f32.f16.f16.f32 "
        "{%0,%1,%2,%3}, {%4,%5,%6,%7}, {%8,%9}, {%0,%1,%2,%3};"
        : "+f"(c[0]), "+f"(c[1]), "+f"(c[2]), "+f"(c[3])
        : "r"(a[0]), "r"(a[1]), "r"(a[2]), "r"(a[3]), "r"(b[0]), "r"(b[1]));
}
__device__ __forceinline__ void cp_async16(uint32_t dst, const void* src, int sz) {
    asm volatile("cp.async.ca.shared.global [%0], [%1], 16, %2;"
                 :: "r"(dst), "l"(src), "r"(sz) : "memory");
}
__device__ __forceinline__ float4 h4_to_f4(uint2 u) {
    __half2 a = *(__half2*)&u.x, b = *(__half2*)&u.y;
    float2 fa = __half22float2(a), fb = __half22float2(b);
    return make_float4(fa.x, fa.y, fb.x, fb.y);
}

// ---------------- prep: fp32 -> bf16 hi/lo splits (+ zero g_S and out) ----------------
__global__ void split_x_kernel(const float* __restrict__ x, float* __restrict__ out) {
    int i = blockIdx.x * blockDim.x + threadIdx.x;
    if (i < 3 * NN * NH) g_S[i] = make_float2(0.f, 0.f);
    if (i >= NN * INDIM / 4) return;
    ((float4*)out)[i] = make_float4(0.f, 0.f, 0.f, 0.f);   // NN*OUTD/4 == NN*INDIM/4
    float4 v = ((const float4*)x)[i];
    __nv_bfloat16 h[4], l[4];
    float f[4] = {v.x, v.y, v.z, v.w};
#pragma unroll
    for (int j = 0; j < 4; j++) {
        h[j] = __float2bfloat16(f[j]);
        l[j] = __float2bfloat16(f[j] - __bfloat162float(h[j]));
    }
    ((uint2*)g_xhi)[i] = *(uint2*)h;
    ((uint2*)g_xlo)[i] = *(uint2*)l;
}

__global__ void split_w_kernel(const float* __restrict__ Wk,
                               const float* __restrict__ Wq,
                               const float* __restrict__ Wv) {
    int i = blockIdx.x * blockDim.x + threadIdx.x;   // i = c*256 + k
    if (i >= 768 * INDIM) return;
    int c = i >> 8, k = i & 255;
    const float* W = (c < 256) ? Wk : ((c < 512) ? Wq : Wv);
    float v = W[k * 256 + (c & 255)];
    __nv_bfloat16 h = __float2bfloat16(v);
    __nv_bfloat16 l = __float2bfloat16(v - __bfloat162float(h));
    g_wthi[i] = h;
    g_wtlo[i] = l;
}

// transpose + fp16-split the 72 transform matrices:
// g_Bt[h*288 + sg*96 + c][d] = M_sg[v][h][d][f]  with c = v*32 + f
__global__ void prep_bt_kernel(const float* __restrict__ cau_filter,
                               const float* __restrict__ msg,
                               const float* __restrict__ msg_cau) {
    int i = blockIdx.x * blockDim.x + threadIdx.x;
    if (i >= NH * 288 * 32) return;
    int d = i & 31;
    int rowg = i >> 5;               // h*288 + sg*96 + c
    int h = rowg / 288;
    int r = rowg % 288;
    int sg = r / 96;
    int c = r % 96;
    int v = c >> 5, f = c & 31;
    const float* M = (sg == 0) ? cau_filter : ((sg == 1) ? msg : msg_cau);
    float val = M[(v * NH + h) * 1024 + d * 32 + f];
    __half hi = __float2half(val);
    __half lo = __float2half(val - __half2float(hi));
    g_Bth[i] = hi;
    g_Btl[i] = lo;
}

// ---------------- kernel 1: QKV GEMM via mma.sync bf16x3, cp.async 2-stage ----------------
#define STAGE_BYTES 40960
__global__ void __launch_bounds__(256, 2) gemm_mma(
    const float* __restrict__ bk, const float* __restrict__ bq, const float* __restrict__ bv)
{
    extern __shared__ __align__(16) unsigned char smdyn[];
    const int AHI = 0, ALO = 10240, BHI = 20480, BLO = 30720;

    int tid = threadIdx.x;
    int lane = tid & 31, wid = tid >> 5;
    int warp_m = wid >> 2;
    int warp_n = wid & 3;
    int mbase = blockIdx.y * 128;
    int nbg = blockIdx.x * 128;

    uint32_t sb = smem_to_u32(smdyn);

    float acc[4][4][4];
#pragma unroll
    for (int nt = 0; nt < 4; nt++)
#pragma unroll
        for (int mt = 0; mt < 4; mt++)
#pragma unroll
            for (int j = 0; j < 4; j++) acc[nt][mt][j] = 0.0f;

#define LOAD_CHUNK(chunk, stage) do {                                               \
        int _k0 = (chunk) * 32;                                                     \
        uint32_t _s0 = sb + (stage) * STAGE_BYTES;                                  \
        _Pragma("unroll")                                                           \
        for (int _j = 0; _j < 2; _j++) {                                            \
            int _c = tid + _j * 256;                                                \
            int _row = _c >> 2, _seg = _c & 3;                                      \
            uint32_t _so = (uint32_t)(_row * 80 + _seg * 16);                       \
            int _gn = mbase + _row;                                                 \
            int _ok = (_gn < NN);                                                   \
            const unsigned char* _pah = (const unsigned char*)(g_xhi + (size_t)(_ok ? _gn : 0) * INDIM + _k0) + _seg * 16; \
            const unsigned char* _pal = (const unsigned char*)(g_xlo + (size_t)(_ok ? _gn : 0) * INDIM + _k0) + _seg * 16; \
            cp_async16(_s0 + AHI + _so, _pah, _ok ? 16 : 0);                        \
            cp_async16(_s0 + ALO + _so, _pal, _ok ? 16 : 0);                        \
            const unsigned char* _pbh = (const unsigned char*)(g_wthi + (size_t)(nbg + _row) * INDIM + _k0) + _seg * 16; \
            const unsigned char* _pbl = (const unsigned char*)(g_wtlo + (size_t)(nbg + _row) * INDIM + _k0) + _seg * 16; \
            cp_async16(_s0 + BHI + _so, _pbh, 16);                                  \
            cp_async16(_s0 + BLO + _so, _pbl, 16);                                  \
        }                                                                           \
        asm volatile("cp.async.commit_group;" ::: "memory");                        \
    } while (0)

    LOAD_CHUNK(0, 0);

    for (int chunk = 0; chunk < 8; chunk++) {
        if (chunk + 1 < 8) {
            LOAD_CHUNK(chunk + 1, (chunk + 1) & 1);
            asm volatile("cp.async.wait_group 1;" ::: "memory");
        } else {
            asm volatile("cp.async.wait_group 0;" ::: "memory");
        }
        __syncthreads();

        uint32_t s0 = sb + (chunk & 1) * STAGE_BYTES;
#pragma unroll
        for (int ks = 0; ks < 2; ks++) {
            uint32_t bh[2][4], bl[2][4];
            int boff = ks * 32 + ((lane >> 3) & 1) * 16;
#pragma unroll
            for (int np = 0; np < 2; np++) {
                int br = warp_n * 32 + np * 16 + ((lane >> 4) & 1) * 8 + (lane & 7);
                uint32_t baddr = s0 + BHI + (uint32_t)(br * 80) + boff;
                ldsm_x4(bh[np], baddr);
                ldsm_x4(bl[np], baddr + (BLO - BHI));
            }
            int aoff = ks * 32 + ((lane >> 4) & 1) * 16;
#pragma unroll
            for (int mt = 0; mt < 4; mt++) {
                uint32_t ah[4], al[4];
                uint32_t addr = s0 + AHI + (uint32_t)((warp_m * 64 + mt * 16 + (lane & 15)) * 80) + aoff;
                ldsm_x4(ah, addr);
                ldsm_x4(al, addr + (ALO - AHI));
#pragma unroll
                for (int np = 0; np < 2; np++)
#pragma unroll
                    for (int sub = 0; sub < 2; sub++) {
                        int nt = np * 2 + sub;
                        mma_bf16(acc[nt][mt], ah, &bh[np][sub * 2]);
                        mma_bf16(acc[nt][mt], ah, &bl[np][sub * 2]);
                        mma_bf16(acc[nt][mt], al, &bh[np][sub * 2]);
                    }
            }
        }
        __syncthreads();
    }

    // epilogue: Q -> fp32; K -> fp16 hi (g_KMh) + lo (g_Klo); V -> fp16 hi/lo
    int buf = nbg >> 8;
    int col0 = (nbg & 255) + warp_n * 32;

#pragma unroll
    for (int mt = 0; mt < 4; mt++) {
        int r0 = mbase + warp_m * 64 + mt * 16 + (lane >> 2);
#pragma unroll
        for (int nt = 0; nt < 4; nt++) {
            int c = col0 + nt * 8 + (lane & 3) * 2;
#pragma unroll
            for (int half = 0; half < 2; half++) {
                int r = r0 + half * 8;
                if (r >= NN) continue;
                float ox, oy;
                if (buf == 0) {
                    float2 bb = *(const float2*)&bk[c];
                    ox = acc[nt][mt][half * 2 + 0] + bb.x;
                    oy = acc[nt][mt][half * 2 + 1] + bb.y;
                    __half hx = __float2half(ox), hy = __float2half(oy);
                    *(__half2*)&g_KMh[(size_t)r * 512 + c] = __halves2half2(hx, hy);
                    *(__half2*)&g_Klo[(size_t)r * 256 + c] = __halves2half2(
                        __float2half(ox - __half2float(hx)),
                        __float2half(oy - __half2float(hy)));
                } else if (buf == 1) {
                    float2 bb = *(const float2*)&bq[c];
                    ox = acc[nt][mt][half * 2 + 0] + bb.x;
                    oy = acc[nt][mt][half * 2 + 1] + bb.y;
                    *(float2*)&g_Q[(size_t)r * OUTD + c] = make_float2(ox, oy);
                } else {
                    float2 bb = *(const float2*)&bv[c];
                    ox = acc[nt][mt][half * 2 + 0] + bb.x;
                    oy = acc[nt][mt][half * 2 + 1] + bb.y;
                    __half hx = __float2half(ox), hy = __float2half(oy);
                    *(__half2*)&g_Vhi[(size_t)r * 256 + c] = __halves2half2(hx, hy);
                    *(__half2*)&g_Vlo[(size_t)r * 256 + c] = __halves2half2(
                        __float2half(ox - __half2float(hx)),
                        __float2half(oy - __half2float(hy)));
                }
            }
        }
    }
}

// ---------------- kernel 2: transform via mma.sync fp16x3 ----------------
// Block = (128-node tile, head). 3 warps: warp 0: mk (A=K, predicated by ct);
// warp 1: val (A=V); warp 2: cval (A=V+te). Each: [128x32] @ [32x96].
// smem: A tiles 6 x 128x80B (Khi,Klo,Vhi,Vlo,VThi,VTlo) = 61440
//       B tiles hi 3x96x80B = 23040, lo 23040 ; ct 512  -> total 108032
#define TSMEM_TOTAL 108032
__global__ void __launch_bounds__(96, 2) transform_mma(
    const float* __restrict__ time_emb, const int* __restrict__ cau_type)
{
    extern __shared__ __align__(16) unsigned char tsm[];
    uint32_t sb = smem_to_u32(tsm);
    const int BOFF = 61440, CTOFF = 107520;
    int tid = threadIdx.x;
    int lane = tid & 31, w = tid >> 5;     // w = source group
    int h = blockIdx.y;
    int nb = blockIdx.x * 128;
    int* ct_s = (int*)(tsm + CTOFF);

    // A tiles: Khi(0), Klo(1), Vhi(2), Vlo(3) via cp.async; 2048 16B segs
    for (int i = tid; i < 2048; i += 96) {
        int tile = i >> 9, rem = i & 511;
        int r = rem >> 2, s = rem & 3;
        int gn = nb + r;
        int ok = (gn < NN);
        int gs = ok ? gn : 0;
        const unsigned char* src;
        if (tile == 0)      src = (const unsigned char*)(g_KMh + (size_t)gs * 512 + h * 32) + s * 16;
        else if (tile == 1) src = (const unsigned char*)(g_Klo + (size_t)gs * 256 + h * 32) + s * 16;
        else if (tile == 2) src = (const unsigned char*)(g_Vhi + (size_t)gs * 256 + h * 32) + s * 16;
        else                src = (const unsigned char*)(g_Vlo + (size_t)gs * 256 + h * 32) + s * 16;
        cp_async16(sb + tile * 10240 + (uint32_t)(r * 80 + s * 16), src, ok ? 16 : 0);
    }
    // B tiles: 288 rows hi + 288 rows lo, 4 segs each
    for (int i = tid; i < 2304; i += 96) {
        int comp = (i >= 1152);
        int j = comp ? i - 1152 : i;
        int r = j >> 2, s = j & 3;      // r in 0..287
        const __half* srcb = comp ? g_Btl : g_Bth;
        const unsigned char* src = (const unsigned char*)(srcb + (size_t)(h * 288 + r) * 32) + s * 16;
        cp_async16(sb + BOFF + comp * 23040 + (uint32_t)(r * 80 + s * 16), src, 16);
    }
    asm volatile("cp.async.commit_group;" ::: "memory");
    for (int i = tid; i < 128; i += 96) {
        int gn = nb + i;
        ct_s[i] = (gn < NN) ? cau_type[gn] : -1;
    }
    asm volatile("cp.async.wait_group 0;" ::: "memory");
    __syncthreads();

    // build VT tiles (4,5): VT = Vhi+Vlo+te, re-split
    for (int i = tid; i < 4096; i += 96) {
        int r = i >> 5, d = i & 31;
        float vh = __half2float(*(__half*)(tsm + 2 * 10240 + r * 80 + d * 2));
        float vl = __half2float(*(__half*)(tsm + 3 * 10240 + r * 80 + d * 2));
        float v = vh + vl + time_emb[h * 32 + d];
        __half hi = __float2half(v);
        __half lo = __float2half(v - __half2float(hi));
        *(__half*)(tsm + 4 * 10240 + r * 80 + d * 2) = hi;
        *(__half*)(tsm + 5 * 10240 + r * 80 + d * 2) = lo;
    }
    __syncthreads();

    // mma: warp w, A tiles hi = w*2 (K:0, V:2, VT:4), B group w
    uint32_t a_hi = sb + (uint32_t)((w == 0 ? 0 : (w == 1 ? 2 : 4)) * 10240);
    uint32_t b_hi = sb + BOFF + (uint32_t)(w * 96 * 80);

#pragma unroll 1
    for (int mt = 0; mt < 8; mt++) {
        float acc[12][4];
#pragma unroll
        for (int nt = 0; nt < 12; nt++)
#pragma unroll
            for (int j = 0; j < 4; j++) acc[nt][j] = 0.0f;

        uint32_t ah[2][4], al[2][4];
#pragma unroll
        for (int ks = 0; ks < 2; ks++) {
            uint32_t aaddr = a_hi + (uint32_t)((mt * 16 + (lane & 15)) * 80) + ks * 32 + ((lane >> 4) & 1) * 16;
            ldsm_x4(ah[ks], aaddr);
            ldsm_x4(al[ks], aaddr + 10240);
        }
#pragma unroll
        for (int ks = 0; ks < 2; ks++) {
            int boff = ks * 32 + ((lane >> 3) & 1) * 16;
#pragma unroll
            for (int np = 0; np < 6; np++) {
                uint32_t bh[4], bl[4];
                int br = np * 16 + ((lane >> 4) & 1) * 8 + (lane & 7);
                uint32_t baddr = b_hi + (uint32_t)(br * 80) + boff;
                ldsm_x4(bh, baddr);
                ldsm_x4(bl, baddr + 23040);
#pragma unroll
                for (int sub = 0; sub < 2; sub++) {
                    int nt = np * 2 + sub;
                    mma_f16(acc[nt], ah[ks], &bh[sub * 2]);
                    mma_f16(acc[nt], ah[ks], &bl[sub * 2]);
                    mma_f16(acc[nt], al[ks], &bh[sub * 2]);
                }
            }
        }

        // store
        int row = lane >> 2;
        int lr0 = mt * 16 + row;
        int gn0 = nb + lr0, gn1 = gn0 + 8;
#pragma unroll
        for (int nt = 0; nt < 12; nt++) {
            int col = nt * 8 + (lane & 3) * 2;
            int e = col >> 5, dim = col & 31;
            __half2 v0 = __floats2half2_rn(acc[nt][0], acc[nt][1]);
            __half2 v1 = __floats2half2_rn(acc[nt][2], acc[nt][3]);
            if (w == 0) {
                if (gn0 < NN && ct_s[lr0] == e)
                    *(__half2*)&g_KMh[(size_t)gn0 * 512 + 256 + h * 32 + dim] = v0;
                if (gn1 < NN && ct_s[lr0 + 8] == e)
                    *(__half2*)&g_KMh[(size_t)gn1 * 512 + 256 + h * 32 + dim] = v1;
            } else {
                size_t off = (w == 1) ? 0 : 256;
                if (gn0 < NN)
                    *(__half2*)&g_VC[((size_t)e * NN + gn0) * 512 + off + h * 32 + dim] = v0;
                if (gn1 < NN)
                    *(__half2*)&g_VC[((size_t)e * NN + gn1) * 512 + off + h * 32 + dim] = v1;
            }
        }
    }
}

// ---------------- kernel 3: edge logits + softmax denominators ----------------
__global__ void __launch_bounds__(256) logits_kernel(
    const int* __restrict__ src, const int* __restrict__ dst,
    const float* __restrict__ pri, const float* __restrict__ pri_cau)
{
    int e = blockIdx.y;
    int edge = blockIdx.x * 8 + (threadIdx.x >> 5);
    if (edge >= EE) return;
    int lane = threadIdx.x & 31;
    int s = src[e * EE + edge];
    int d = dst[e * EE + edge];
    int off = lane * 4;

    const float* qp = g_Q + d * OUTD;
    const __half* kmp = g_KMh + (size_t)s * 512;
    float4 qa = *(const float4*)(qp + off);
    float4 qb = *(const float4*)(qp + 128 + off);
    float4 ka = h4_to_f4(*(const uint2*)(kmp + off));
    float4 kb = h4_to_f4(*(const uint2*)(kmp + 128 + off));
    float4 ma = h4_to_f4(*(const uint2*)(kmp + 256 + off));
    float4 mb = h4_to_f4(*(const uint2*)(kmp + 384 + off));

    float p0 = dot4(qa, ka);
    float p1 = dot4(qb, kb);
    float m0 = dot4(qa, ma);
    float m1 = dot4(qb, mb);

    int odd = lane & 1;
    float pv = odd ? p0 : p1;
    float mv = odd ? m0 : m1;
    float pr = __shfl_xor_sync(0xffffffffu, pv, 1);
    float mr = __shfl_xor_sync(0xffffffffu, mv, 1);
    float P = (odd ? p1 : p0) + pr;
    float M = (odd ? m1 : m0) + mr;
    P += __shfl_xor_sync(0xffffffffu, P, 2);
    M += __shfl_xor_sync(0xffffffffu, M, 2);
    P += __shfl_xor_sync(0xffffffffu, P, 4);
    M += __shfl_xor_sync(0xffffffffu, M, 4);

    int hh = (lane >> 3) + (odd << 2);
    const float isdk = 0.17677669529663687f;  // 1/sqrt(32)
    float ea = __expf(P * pri[e * NH + hh] * isdk);
    float ec = __expf(M * pri_cau[e * NH + hh] * isdk);

    int srcl = (lane & 3) * 8 + ((lane >> 2) & 1);
    float va = __shfl_sync(0xffffffffu, ea, srcl);
    float vc = __shfl_sync(0xffffffffu, ec, srcl);

    if (lane < NH) {
        int eidx = e * EE + edge;
        g_E[eidx * NH + lane] = make_float2(va, vc);
        red_add_v2(&g_S[(e * NN + d) * NH + lane], va, vc);
    }
}

// ---------------- kernel 4: weighted aggregation (fp16 VC gathers) ----------------
__global__ void __launch_bounds__(256) aggregate_kernel(
    const int* __restrict__ src, const int* __restrict__ dst,
    const float* __restrict__ comb_pri, float* __restrict__ out)
{
    int e = blockIdx.y;
    int edge = blockIdx.x * 8 + (threadIdx.x >> 5);
    if (edge >= EE) return;
    int lane = threadIdx.x & 31;
    int s = src[e * EE + edge];
    int d = dst[e * EE + edge];
    int h0 = lane >> 3;
    int h1 = h0 + 4;
    int eidx = e * EE + edge;

    float2 eh0 = g_E[eidx * NH + h0];
    float2 eh1 = g_E[eidx * NH + h1];
    float2 s0 = g_S[(e * NN + d) * NH + h0];
    float2 s1 = g_S[(e * NN + d) * NH + h1];
    float wa0 = __fdividef(eh0.x, s0.x);
    float wc0 = __fdividef(eh0.y, s0.y);
    float wa1 = __fdividef(eh1.x, s1.x);
    float wc1 = __fdividef(eh1.y, s1.y);

    int off = lane * 4;
    const __half* vp = g_VC + ((size_t)e * NN + s) * 512;
    float4 v0 = h4_to_f4(*(const uint2*)(vp + off));
    float4 v1 = h4_to_f4(*(const uint2*)(vp + 128 + off));
    float4 c0 = h4_to_f4(*(const uint2*)(vp + 256 + off));
    float4 c1 = h4_to_f4(*(const uint2*)(vp + 384 + off));
    float4 b0 = *(const float4*)&comb_pri[e * OUTD + off];
    float4 b1 = *(const float4*)&comb_pri[e * OUTD + 128 + off];

    float r0 = wa0 * v0.x + wc0 * b0.x * c0.x;
    float r1 = wa0 * v0.y + wc0 * b0.y * c0.y;
    float r2 = wa0 * v0.z + wc0 * b0.z * c0.z;
    float r3 = wa0 * v0.w + wc0 * b0.w * c0.w;
    float r4 = wa1 * v1.x + wc1 * b1.x * c1.x;
    float r5 = wa1 * v1.y + wc1 * b1.y * c1.y;
    float r6 = wa1 * v1.z + wc1 * b1.z * c1.z;
    float r7 = wa1 * v1.w + wc1 * b1.w * c1.w;

    float* op = out + d * OUTD;
    red_add_v4(op + off, r0, r1, r2, r3);
    red_add_v4(op + 128 + off, r4, r5, r6, r7);
}

// ---------------- kernel 5: finalize (mean over 3 etypes + relu) ----------------
__global__ void finalize_kernel(float* __restrict__ out) {
    int i = blockIdx.x * blockDim.x + threadIdx.x;
    if (i < NN * OUTD) {
        float v = out[i] * (1.0f / 3.0f);
        out[i] = v > 0.0f ? v : 0.0f;
    }
}

// ---------------- launch ----------------
extern "C" void kernel_launch(void* const* d_in, const int* in_sizes, int n_in,
                              void* d_out, int out_size) {
    const float* x          = (const float*)d_in[0];
    const float* Wk         = (const float*)d_in[1];
    const float* bk         = (const float*)d_in[2];
    const float* Wq         = (const float*)d_in[3];
    const float* bq         = (const float*)d_in[4];
    const float* Wv         = (const float*)d_in[5];
    const float* bv         = (const float*)d_in[6];
    const float* pri        = (const float*)d_in[7];
    const float* msg        = (const float*)d_in[8];
    const float* pri_cau    = (const float*)d_in[9];
    const float* msg_cau    = (const float*)d_in[10];
    const float* comb_pri   = (const float*)d_in[11];
    const float* cau_filter = (const float*)d_in[12];
    const float* time_emb   = (const float*)d_in[13];
    const int*   cau_type   = (const int*)d_in[14];
    const int*   src        = (const int*)d_in[15];
    const int*   dst        = (const int*)d_in[16];
    float* out = (float*)d_out;

    split_x_kernel<<<(NN * INDIM / 4 + 255) / 256, 256>>>(x, out);
    split_w_kernel<<<768, 256>>>(Wk, Wq, Wv);
    prep_bt_kernel<<<(NH * 288 * 32 + 255) / 256, 256>>>(cau_filter, msg, msg_cau);

    cudaFuncSetAttribute(gemm_mma, cudaFuncAttributeMaxDynamicSharedMemorySize,
                         2 * STAGE_BYTES);
    gemm_mma<<<dim3(6, 157), 256, 2 * STAGE_BYTES>>>(bk, bq, bv);

    cudaFuncSetAttribute(transform_mma, cudaFuncAttributeMaxDynamicSharedMemorySize,
                         TSMEM_TOTAL);
    transform_mma<<<dim3(157, NH), 96, TSMEM_TOTAL>>>(time_emb, cau_type);

    dim3 egrid((EE + 7) / 8, 3);
    logits_kernel<<<egrid, 256>>>(src, dst, pri, pri_cau);
    aggregate_kernel<<<egrid, 256>>>(src, dst, comb_pri, out);

    finalize_kernel<<<(NN * OUTD + 255) / 256, 256>>>(out);
}